// round 2
// baseline (speedup 1.0000x reference)
#include <cuda_runtime.h>
#include <cstdint>

#define RES   128
#define FEAT  32
#define OUTF  4
#define NVOX  (RES * RES * RES)           // 2,097,152 voxels
#define NPTS  (2048 * 1024)               // 2,097,152 points
#define PTS_PER_BLOCK 256

// Voxel-major scratch: vox[v*32 + c], one 128B line per voxel.
__device__ float g_vox[(size_t)NVOX * FEAT];

// MLP weights in constant memory: unrolled, warp-uniform, compile-time-indexed
// accesses compile to LDCU (uniform-const port) — zero L1tex traffic.
__constant__ float c_w1[FEAT * FEAT];
__constant__ float c_w2[FEAT * FEAT];
__constant__ float c_w3[FEAT * FEAT];
__constant__ float c_w4[OUTF * FEAT];
__constant__ float c_b1[FEAT];
__constant__ float c_b2[FEAT];
__constant__ float c_b3[FEAT];
__constant__ float c_b4[OUTF];

// ---------------------------------------------------------------------------
// Kernel 1: transpose grid (C, D, H, W) -> (D*H*W, C)
// ---------------------------------------------------------------------------
__global__ void __launch_bounds__(256) transpose_grid_kernel(const float* __restrict__ g) {
    __shared__ float tile[32][33];
    const int v0 = blockIdx.x * 32;
    const int tx = threadIdx.x;   // 0..31
    const int ty = threadIdx.y;   // 0..7

#pragma unroll
    for (int i = 0; i < 4; i++) {
        int c = ty + i * 8;
        tile[c][tx] = g[(size_t)c * NVOX + v0 + tx];   // coalesced along voxels
    }
    __syncthreads();
#pragma unroll
    for (int i = 0; i < 4; i++) {
        int v = ty + i * 8;
        g_vox[(size_t)(v0 + v) * FEAT + tx] = tile[tx][v];  // coalesced along channels
    }
}

// ---------------------------------------------------------------------------
// Kernel 2: fused trilinear gather + 4-layer MLP.
// Phase 1: warp-cooperative gather (8 lanes/point, float4 chunks) -> smem.
// Phase 2: per-thread MLP, v/h in registers, weights from constant memory.
// ---------------------------------------------------------------------------
__global__ void __launch_bounds__(256) fused_field_kernel(
    const float* __restrict__ coord,
    float* __restrict__ out)
{
    __shared__ float4 sv[8][PTS_PER_BLOCK];     // [chunk][point]   32 KB

    const int tid = threadIdx.x;

    // --- Phase 1: gather ---
    const int warp  = tid >> 5;
    const int lane  = tid & 31;
    const int chunk = lane & 7;        // which float4 of the 32 channels
    const int psub  = lane >> 3;       // which of 4 points in this round

#pragma unroll 1
    for (int s = 0; s < 8; s++) {
        const int q   = (warp << 5) + (s << 2) + psub;           // point in block
        const int pid = blockIdx.x * PTS_PER_BLOCK + q;

        const float cx = __ldg(&coord[pid * 3 + 0]);
        const float cy = __ldg(&coord[pid * 3 + 1]);
        const float cz = __ldg(&coord[pid * 3 + 2]);

        // fx = ((x+1)*W - 1) * 0.5 = (x+1)*64 - 0.5
        const float fx = (cx + 1.0f) * 64.0f - 0.5f;
        const float fy = (cy + 1.0f) * 64.0f - 0.5f;
        const float fz = (cz + 1.0f) * 64.0f - 0.5f;

        const float x0f = floorf(fx), y0f = floorf(fy), z0f = floorf(fz);
        const float tx = fx - x0f, ty = fy - y0f, tz = fz - z0f;
        const int x0 = (int)x0f, y0 = (int)y0f, z0 = (int)z0f;

        int   xs[2], ys[2], zs[2];
        float wx[2], wy[2], wz[2];
        xs[0] = max(x0, 0);       xs[1] = min(x0 + 1, RES - 1);
        ys[0] = max(y0, 0);       ys[1] = min(y0 + 1, RES - 1);
        zs[0] = max(z0, 0);       zs[1] = min(z0 + 1, RES - 1);
        wx[0] = (x0 >= 0)        ? (1.0f - tx) : 0.0f;
        wx[1] = (x0 + 1 <= RES-1)? tx          : 0.0f;
        wy[0] = (y0 >= 0)        ? (1.0f - ty) : 0.0f;
        wy[1] = (y0 + 1 <= RES-1)? ty          : 0.0f;
        wz[0] = (z0 >= 0)        ? (1.0f - tz) : 0.0f;
        wz[1] = (z0 + 1 <= RES-1)? tz          : 0.0f;

        float4 acc = make_float4(0.f, 0.f, 0.f, 0.f);
#pragma unroll
        for (int kz = 0; kz < 2; kz++) {
#pragma unroll
            for (int ky = 0; ky < 2; ky++) {
#pragma unroll
                for (int kx = 0; kx < 2; kx++) {
                    const float w = wz[kz] * wy[ky] * wx[kx];
                    const int   vox = ((zs[kz] * RES + ys[ky]) * RES + xs[kx]);
                    const float4 gv = __ldg(((const float4*)(g_vox + (size_t)vox * FEAT)) + chunk);
                    acc.x = fmaf(w, gv.x, acc.x);
                    acc.y = fmaf(w, gv.y, acc.y);
                    acc.z = fmaf(w, gv.z, acc.z);
                    acc.w = fmaf(w, gv.w, acc.w);
                }
            }
        }
        sv[chunk][q] = acc;
    }

    __syncthreads();

    // --- Phase 2: MLP (one thread per point), weights via constant memory ---
    const float4* W1 = reinterpret_cast<const float4*>(c_w1);
    const float4* W2 = reinterpret_cast<const float4*>(c_w2);
    const float4* W3 = reinterpret_cast<const float4*>(c_w3);
    const float4* W4 = reinterpret_cast<const float4*>(c_w4);

    float v[32], h[32];
#pragma unroll
    for (int m = 0; m < 8; m++) {
        float4 f = sv[m][tid];
        v[4*m+0] = f.x; v[4*m+1] = f.y; v[4*m+2] = f.z; v[4*m+3] = f.w;
    }

    // layer 1: h = relu(W1 v + b1)
#pragma unroll
    for (int j = 0; j < 32; j++) {
        float a = c_b1[j];
#pragma unroll
        for (int i = 0; i < 8; i++) {
            const float4 ww = W1[j * 8 + i];
            a = fmaf(ww.x, v[4*i+0], a);
            a = fmaf(ww.y, v[4*i+1], a);
            a = fmaf(ww.z, v[4*i+2], a);
            a = fmaf(ww.w, v[4*i+3], a);
        }
        h[j] = fmaxf(a, 0.0f);
    }
    // layer 2: v = relu(W2 h + b2)
#pragma unroll
    for (int j = 0; j < 32; j++) {
        float a = c_b2[j];
#pragma unroll
        for (int i = 0; i < 8; i++) {
            const float4 ww = W2[j * 8 + i];
            a = fmaf(ww.x, h[4*i+0], a);
            a = fmaf(ww.y, h[4*i+1], a);
            a = fmaf(ww.z, h[4*i+2], a);
            a = fmaf(ww.w, h[4*i+3], a);
        }
        v[j] = fmaxf(a, 0.0f);
    }
    // layer 3: h = relu(W3 v + b3)
#pragma unroll
    for (int j = 0; j < 32; j++) {
        float a = c_b3[j];
#pragma unroll
        for (int i = 0; i < 8; i++) {
            const float4 ww = W3[j * 8 + i];
            a = fmaf(ww.x, v[4*i+0], a);
            a = fmaf(ww.y, v[4*i+1], a);
            a = fmaf(ww.z, v[4*i+2], a);
            a = fmaf(ww.w, v[4*i+3], a);
        }
        h[j] = fmaxf(a, 0.0f);
    }
    // layer 4: out = W4 h + b4  (4 outputs)
    float o[4];
#pragma unroll
    for (int j = 0; j < 4; j++) {
        float a = c_b4[j];
#pragma unroll
        for (int i = 0; i < 8; i++) {
            const float4 ww = W4[j * 8 + i];
            a = fmaf(ww.x, h[4*i+0], a);
            a = fmaf(ww.y, h[4*i+1], a);
            a = fmaf(ww.z, h[4*i+2], a);
            a = fmaf(ww.w, h[4*i+3], a);
        }
        o[j] = a;
    }

    const int pid = blockIdx.x * PTS_PER_BLOCK + tid;
    ((float4*)out)[pid] = make_float4(o[0], o[1], o[2], o[3]);
}

// ---------------------------------------------------------------------------
extern "C" void kernel_launch(void* const* d_in, const int* in_sizes, int n_in,
                              void* d_out, int out_size)
{
    const float* coord = (const float*)d_in[0];
    const float* grid  = (const float*)d_in[1];

    // Weights/biases -> constant memory (D2D memcpy nodes; graph-capturable)
    cudaMemcpyToSymbolAsync(c_w1, d_in[2], FEAT * FEAT * sizeof(float), 0, cudaMemcpyDeviceToDevice, 0);
    cudaMemcpyToSymbolAsync(c_b1, d_in[3], FEAT * sizeof(float),        0, cudaMemcpyDeviceToDevice, 0);
    cudaMemcpyToSymbolAsync(c_w2, d_in[4], FEAT * FEAT * sizeof(float), 0, cudaMemcpyDeviceToDevice, 0);
    cudaMemcpyToSymbolAsync(c_b2, d_in[5], FEAT * sizeof(float),        0, cudaMemcpyDeviceToDevice, 0);
    cudaMemcpyToSymbolAsync(c_w3, d_in[6], FEAT * FEAT * sizeof(float), 0, cudaMemcpyDeviceToDevice, 0);
    cudaMemcpyToSymbolAsync(c_b3, d_in[7], FEAT * sizeof(float),        0, cudaMemcpyDeviceToDevice, 0);
    cudaMemcpyToSymbolAsync(c_w4, d_in[8], OUTF * FEAT * sizeof(float), 0, cudaMemcpyDeviceToDevice, 0);
    cudaMemcpyToSymbolAsync(c_b4, d_in[9], OUTF * sizeof(float),        0, cudaMemcpyDeviceToDevice, 0);

    float* out = (float*)d_out;

    // 1) transpose grid into voxel-major scratch
    dim3 tb(32, 8);
    transpose_grid_kernel<<<NVOX / 32, tb>>>(grid);

    // 2) fused gather + MLP
    fused_field_kernel<<<NPTS / PTS_PER_BLOCK, PTS_PER_BLOCK>>>(coord, out);
}

// round 3
// speedup vs baseline: 1.4985x; 1.4985x over previous
#include <cuda_runtime.h>
#include <cstdint>

#define RES   128
#define FEAT  32
#define NVOX  (RES * RES * RES)           // 2,097,152 voxels
#define NPTS  (2048 * 1024)               // 2,097,152 points
#define FULLM 0xffffffffu

// Voxel-major scratch: vox[v*32 + c], one 128B line per voxel.
__device__ float g_vox[(size_t)NVOX * FEAT];
// Pre-split, lane-major tf32 weight B-fragments:
// frags 0..47: layer l (0..2), idx l*16 + kt*4 + nt ; frags 48..51: layer 3, idx 48+kt.
// Each frag: 32 lanes x {b0hi, b1hi, b0lo, b1lo}.
__device__ float g_wfrag[52 * 128];

// ---------------------------------------------------------------------------
// Kernel 1: transpose grid (C, D, H, W) -> (D*H*W, C)
// ---------------------------------------------------------------------------
__global__ void __launch_bounds__(256) transpose_grid_kernel(const float* __restrict__ g) {
    __shared__ float tile[32][33];
    const int v0 = blockIdx.x * 32;
    const int tx = threadIdx.x;   // 0..31
    const int ty = threadIdx.y;   // 0..7
#pragma unroll
    for (int i = 0; i < 4; i++) {
        int c = ty + i * 8;
        tile[c][tx] = g[(size_t)c * NVOX + v0 + tx];
    }
    __syncthreads();
#pragma unroll
    for (int i = 0; i < 4; i++) {
        int v = ty + i * 8;
        g_vox[(size_t)(v0 + v) * FEAT + tx] = tile[tx][v];
    }
}

// ---------------------------------------------------------------------------
// Kernel 1b: build split-tf32 weight B-fragments in mma lane order.
// B (k8 x n8, col-major fragment): b0 = W[n=8nt+g][k=8kt+t], b1 = same k+4.
// ---------------------------------------------------------------------------
__global__ void prep_wfrag_kernel(const float* __restrict__ w1, const float* __restrict__ w2,
                                  const float* __restrict__ w3, const float* __restrict__ w4) {
    const int f = blockIdx.x;        // 0..51
    const int lane = threadIdx.x;    // 0..31
    const int g = lane >> 2, t = lane & 3;
    float b0, b1;
    if (f < 48) {
        const int l = f >> 4, r = f & 15, kt = r >> 2, nt = r & 3;
        const float* W = (l == 0) ? w1 : (l == 1) ? w2 : w3;
        b0 = W[(8 * nt + g) * 32 + 8 * kt + t];
        b1 = W[(8 * nt + g) * 32 + 8 * kt + t + 4];
    } else {
        const int kt = f - 48;
        b0 = (g < 4) ? w4[g * 32 + 8 * kt + t]     : 0.0f;
        b1 = (g < 4) ? w4[g * 32 + 8 * kt + t + 4] : 0.0f;
    }
    const uint32_t h0 = __float_as_uint(b0) & 0xffffe000u;
    const uint32_t h1 = __float_as_uint(b1) & 0xffffe000u;
    float4 v;
    v.x = __uint_as_float(h0);
    v.y = __uint_as_float(h1);
    v.z = b0 - v.x;
    v.w = b1 - v.y;
    *(float4*)&g_wfrag[f * 128 + lane * 4] = v;
}

// ---------------------------------------------------------------------------
__device__ __forceinline__ void mma_tf32(float d[4],
                                         uint32_t a0, uint32_t a1, uint32_t a2, uint32_t a3,
                                         uint32_t b0, uint32_t b1) {
    asm volatile("mma.sync.aligned.m16n8k8.row.col.f32.tf32.tf32.f32 "
                 "{%0,%1,%2,%3}, {%4,%5,%6,%7}, {%8,%9}, {%0,%1,%2,%3};"
                 : "+f"(d[0]), "+f"(d[1]), "+f"(d[2]), "+f"(d[3])
                 : "r"(a0), "r"(a1), "r"(a2), "r"(a3), "r"(b0), "r"(b1));
}

__device__ __forceinline__ void split1(float x, uint32_t& h, uint32_t& l) {
    h = __float_as_uint(x) & 0xffffe000u;
    l = __float_as_uint(x - __uint_as_float(h));
}

// One MLP layer on mma, A built from previous D via warp shuffles.
// D layout (m16n8 acc): c0=(g,2t) c1=(g,2t+1) c2=(g+8,2t) c3=(g+8,2t+1).
// A layout (m16k8 tf32): a0=(g,t) a1=(g+8,t) a2=(g,t+4) a3=(g+8,t+4).
template <int L, int NT>
__device__ __forceinline__ void mlp_layer_shfl(const float D[2][4][4], float Dn[2][4][4],
                                               const float* __restrict__ swf,
                                               const float* __restrict__ sb, int lane) {
    const int t = lane & 3;
    const int src0 = (lane & ~3) | (t >> 1);
    const int src2 = src0 + 2;
    const bool odd = (t & 1) != 0;

#pragma unroll
    for (int mt = 0; mt < 2; mt++)
#pragma unroll
        for (int nt = 0; nt < NT; nt++) {
            const float2 bb = *(const float2*)&sb[L * 32 + 8 * nt + 2 * t];
            Dn[mt][nt][0] = bb.x; Dn[mt][nt][1] = bb.y;
            Dn[mt][nt][2] = bb.x; Dn[mt][nt][3] = bb.y;
        }
#pragma unroll
    for (int kt = 0; kt < 4; kt++) {
        uint32_t ah[2][4], al[2][4];
#pragma unroll
        for (int mt = 0; mt < 2; mt++) {
            const float r0 = D[mt][kt][0], r1 = D[mt][kt][1];
            const float r2 = D[mt][kt][2], r3 = D[mt][kt][3];
            const float e0 = __shfl_sync(FULLM, r0, src0);
            const float o0 = __shfl_sync(FULLM, r1, src0);
            const float e1 = __shfl_sync(FULLM, r2, src0);
            const float o1 = __shfl_sync(FULLM, r3, src0);
            const float e2 = __shfl_sync(FULLM, r0, src2);
            const float o2 = __shfl_sync(FULLM, r1, src2);
            const float e3 = __shfl_sync(FULLM, r2, src2);
            const float o3 = __shfl_sync(FULLM, r3, src2);
            split1(odd ? o0 : e0, ah[mt][0], al[mt][0]);
            split1(odd ? o1 : e1, ah[mt][1], al[mt][1]);
            split1(odd ? o2 : e2, ah[mt][2], al[mt][2]);
            split1(odd ? o3 : e3, ah[mt][3], al[mt][3]);
        }
#pragma unroll
        for (int nt = 0; nt < NT; nt++) {
            const int fidx = (L < 3) ? (L * 16 + kt * 4 + nt) : (48 + kt);
            const float4 B = *(const float4*)&swf[fidx * 128 + lane * 4];
            const uint32_t bh0 = __float_as_uint(B.x), bh1 = __float_as_uint(B.y);
            const uint32_t bl0 = __float_as_uint(B.z), bl1 = __float_as_uint(B.w);
#pragma unroll
            for (int mt = 0; mt < 2; mt++) {
                mma_tf32(Dn[mt][nt], ah[mt][0], ah[mt][1], ah[mt][2], ah[mt][3], bh0, bh1);
                mma_tf32(Dn[mt][nt], al[mt][0], al[mt][1], al[mt][2], al[mt][3], bh0, bh1);
                mma_tf32(Dn[mt][nt], ah[mt][0], ah[mt][1], ah[mt][2], ah[mt][3], bl0, bl1);
            }
        }
    }
}

// ---------------------------------------------------------------------------
// smem: [ wfrag 6656 | bias 128 | act 256*36 ] floats = 16000 floats = 64000 B
#define SMEM_FLOATS (52 * 128 + 128 + 256 * 36)
#define SMEM_BYTES  (SMEM_FLOATS * 4)

__global__ void __launch_bounds__(256, 2) fused_field_kernel(
    const float* __restrict__ coord,
    const float* __restrict__ b1g, const float* __restrict__ b2g,
    const float* __restrict__ b3g, const float* __restrict__ b4g,
    float* __restrict__ out)
{
    extern __shared__ float sm[];
    float* swf = sm;                      // 52*128
    float* sb  = sm + 52 * 128;           // 128
    float* svf = sm + 52 * 128 + 128;     // 256 points * stride 36

    const int tid = threadIdx.x;

    // --- stage weights/biases into smem ---
    {
        const float4* src = (const float4*)g_wfrag;
        float4* dst = (float4*)swf;
#pragma unroll
        for (int i = tid; i < 52 * 32; i += 256) dst[i] = src[i];
        if (tid < 32) {
            sb[tid]      = b1g[tid];
            sb[32 + tid] = b2g[tid];
            sb[64 + tid] = b3g[tid];
            sb[96 + tid] = (tid < 4) ? b4g[tid] : 0.0f;
        }
    }
    __syncthreads();

    const int warp  = tid >> 5;
    const int lane  = tid & 31;
    const int chunk = lane & 7;        // float4 slice of 32 channels
    const int psub  = lane >> 3;       // point-of-4 in round

    // --- Phase 1: warp-cooperative trilinear gather -> svf[q*36 + feat] ---
#pragma unroll 1
    for (int s = 0; s < 8; s++) {
        const int q   = (warp << 5) + (s << 2) + psub;
        const int pid = blockIdx.x * 256 + q;

        const float cx = __ldg(&coord[pid * 3 + 0]);
        const float cy = __ldg(&coord[pid * 3 + 1]);
        const float cz = __ldg(&coord[pid * 3 + 2]);

        const float fx = (cx + 1.0f) * 64.0f - 0.5f;
        const float fy = (cy + 1.0f) * 64.0f - 0.5f;
        const float fz = (cz + 1.0f) * 64.0f - 0.5f;

        const float x0f = floorf(fx), y0f = floorf(fy), z0f = floorf(fz);
        const float tx = fx - x0f, ty = fy - y0f, tz = fz - z0f;
        const int x0 = (int)x0f, y0 = (int)y0f, z0 = (int)z0f;

        int   xs[2], ys[2], zs[2];
        float wx[2], wy[2], wz[2];
        xs[0] = max(x0, 0);        xs[1] = min(x0 + 1, RES - 1);
        ys[0] = max(y0, 0);        ys[1] = min(y0 + 1, RES - 1);
        zs[0] = max(z0, 0);        zs[1] = min(z0 + 1, RES - 1);
        wx[0] = (x0 >= 0)          ? (1.0f - tx) : 0.0f;
        wx[1] = (x0 + 1 <= RES - 1)? tx          : 0.0f;
        wy[0] = (y0 >= 0)          ? (1.0f - ty) : 0.0f;
        wy[1] = (y0 + 1 <= RES - 1)? ty          : 0.0f;
        wz[0] = (z0 >= 0)          ? (1.0f - tz) : 0.0f;
        wz[1] = (z0 + 1 <= RES - 1)? tz          : 0.0f;

        float4 acc = make_float4(0.f, 0.f, 0.f, 0.f);
#pragma unroll
        for (int kz = 0; kz < 2; kz++)
#pragma unroll
            for (int ky = 0; ky < 2; ky++)
#pragma unroll
                for (int kx = 0; kx < 2; kx++) {
                    const float w = wz[kz] * wy[ky] * wx[kx];
                    const int   vox = ((zs[kz] * RES + ys[ky]) * RES + xs[kx]);
                    const float4 gv = __ldg(((const float4*)(g_vox + (size_t)vox * FEAT)) + chunk);
                    acc.x = fmaf(w, gv.x, acc.x);
                    acc.y = fmaf(w, gv.y, acc.y);
                    acc.z = fmaf(w, gv.z, acc.z);
                    acc.w = fmaf(w, gv.w, acc.w);
                }
        *(float4*)&svf[q * 36 + chunk * 4] = acc;
    }
    __syncwarp();

    // --- Phase 2: 4-layer MLP on tensor cores (3xTF32) ---
    const int g = lane >> 2, t = lane & 3;
    float D[2][4][4], Dn[2][4][4];

    // layer 1: A fragments from svf (conflict-free: bank = 4g+t)
#pragma unroll
    for (int mt = 0; mt < 2; mt++)
#pragma unroll
        for (int nt = 0; nt < 4; nt++) {
            const float2 bb = *(const float2*)&sb[8 * nt + 2 * t];
            D[mt][nt][0] = bb.x; D[mt][nt][1] = bb.y;
            D[mt][nt][2] = bb.x; D[mt][nt][3] = bb.y;
        }
#pragma unroll
    for (int kt = 0; kt < 4; kt++) {
        uint32_t ah[2][4], al[2][4];
#pragma unroll
        for (int mt = 0; mt < 2; mt++) {
            const int q0 = warp * 32 + 16 * mt + g;
            split1(svf[q0 * 36 + 8 * kt + t],           ah[mt][0], al[mt][0]);
            split1(svf[(q0 + 8) * 36 + 8 * kt + t],     ah[mt][1], al[mt][1]);
            split1(svf[q0 * 36 + 8 * kt + t + 4],       ah[mt][2], al[mt][2]);
            split1(svf[(q0 + 8) * 36 + 8 * kt + t + 4], ah[mt][3], al[mt][3]);
        }
#pragma unroll
        for (int nt = 0; nt < 4; nt++) {
            const float4 B = *(const float4*)&swf[(kt * 4 + nt) * 128 + lane * 4];
            const uint32_t bh0 = __float_as_uint(B.x), bh1 = __float_as_uint(B.y);
            const uint32_t bl0 = __float_as_uint(B.z), bl1 = __float_as_uint(B.w);
#pragma unroll
            for (int mt = 0; mt < 2; mt++) {
                mma_tf32(D[mt][nt], ah[mt][0], ah[mt][1], ah[mt][2], ah[mt][3], bh0, bh1);
                mma_tf32(D[mt][nt], al[mt][0], al[mt][1], al[mt][2], al[mt][3], bh0, bh1);
                mma_tf32(D[mt][nt], ah[mt][0], ah[mt][1], ah[mt][2], ah[mt][3], bl0, bl1);
            }
        }
    }
#pragma unroll
    for (int mt = 0; mt < 2; mt++)
#pragma unroll
        for (int nt = 0; nt < 4; nt++)
#pragma unroll
            for (int i = 0; i < 4; i++) D[mt][nt][i] = fmaxf(D[mt][nt][i], 0.0f);

    // layer 2
    mlp_layer_shfl<1, 4>(D, Dn, swf, sb, lane);
#pragma unroll
    for (int mt = 0; mt < 2; mt++)
#pragma unroll
        for (int nt = 0; nt < 4; nt++)
#pragma unroll
            for (int i = 0; i < 4; i++) Dn[mt][nt][i] = fmaxf(Dn[mt][nt][i], 0.0f);

    // layer 3
    mlp_layer_shfl<2, 4>(Dn, D, swf, sb, lane);
#pragma unroll
    for (int mt = 0; mt < 2; mt++)
#pragma unroll
        for (int nt = 0; nt < 4; nt++)
#pragma unroll
            for (int i = 0; i < 4; i++) D[mt][nt][i] = fmaxf(D[mt][nt][i], 0.0f);

    // layer 4 (4 outputs in n-tile 0, no relu)
    mlp_layer_shfl<3, 1>(D, Dn, swf, sb, lane);

    // store: c0/c1 = (row g, cols 2t,2t+1), c2/c3 = (row g+8); valid cols < 4.
    if (t < 2) {
        const int base = blockIdx.x * 256 + warp * 32;
#pragma unroll
        for (int mt = 0; mt < 2; mt++) {
            const int p0 = base + 16 * mt + g;
            *(float2*)&out[p0 * 4 + 2 * t]       = make_float2(Dn[mt][0][0], Dn[mt][0][1]);
            *(float2*)&out[(p0 + 8) * 4 + 2 * t] = make_float2(Dn[mt][0][2], Dn[mt][0][3]);
        }
    }
}

// ---------------------------------------------------------------------------
extern "C" void kernel_launch(void* const* d_in, const int* in_sizes, int n_in,
                              void* d_out, int out_size)
{
    const float* coord = (const float*)d_in[0];
    const float* grid  = (const float*)d_in[1];
    const float* w1 = (const float*)d_in[2];
    const float* b1 = (const float*)d_in[3];
    const float* w2 = (const float*)d_in[4];
    const float* b2 = (const float*)d_in[5];
    const float* w3 = (const float*)d_in[6];
    const float* b3 = (const float*)d_in[7];
    const float* w4 = (const float*)d_in[8];
    const float* b4 = (const float*)d_in[9];
    float* out = (float*)d_out;

    cudaFuncSetAttribute(fused_field_kernel,
                         cudaFuncAttributeMaxDynamicSharedMemorySize, SMEM_BYTES);

    prep_wfrag_kernel<<<52, 32>>>(w1, w2, w3, w4);

    dim3 tb(32, 8);
    transpose_grid_kernel<<<NVOX / 32, tb>>>(grid);

    fused_field_kernel<<<NPTS / 256, 256, SMEM_BYTES>>>(coord, b1, b2, b3, b4, out);
}

// round 4
// speedup vs baseline: 2.0160x; 1.3453x over previous
#include <cuda_runtime.h>
#include <cuda_fp16.h>
#include <cstdint>

#define RES   128
#define FEAT  32
#define NVOX  (RES * RES * RES)           // 2,097,152 voxels
#define NPTS  (2048 * 1024)               // 2,097,152 points
#define FULLM 0xffffffffu

// fp16 voxel tensor holding layer-1 pre-activations: vox[v*32+j] = (W1 @ g[:,v])[j]
// 134 MB — approximately L2-resident.
__device__ __half g_vox16[(size_t)NVOX * FEAT];
// Pre-split lane-major tf32 weight B-fragments:
// frags 0..15 W1, 16..31 W2, 32..47 W3, 48..51 W4. Each: 32 lanes x {b0hi,b1hi,b0lo,b1lo}.
__device__ float g_wfrag[52 * 128];

// ---------------------------------------------------------------------------
__device__ __forceinline__ void mma_tf32(float d[4],
                                         uint32_t a0, uint32_t a1, uint32_t a2, uint32_t a3,
                                         uint32_t b0, uint32_t b1) {
    asm volatile("mma.sync.aligned.m16n8k8.row.col.f32.tf32.tf32.f32 "
                 "{%0,%1,%2,%3}, {%4,%5,%6,%7}, {%8,%9}, {%0,%1,%2,%3};"
                 : "+f"(d[0]), "+f"(d[1]), "+f"(d[2]), "+f"(d[3])
                 : "r"(a0), "r"(a1), "r"(a2), "r"(a3), "r"(b0), "r"(b1));
}

__device__ __forceinline__ void split1(float x, uint32_t& h, uint32_t& l) {
    h = __float_as_uint(x) & 0xffffe000u;
    l = __float_as_uint(x - __uint_as_float(h));
}

// ---------------------------------------------------------------------------
// Kernel 1: build split-tf32 weight B-fragments in mma lane order.
// B (k8 x n8 col-major frag): b0 = W[n=8nt+g][k=8kt+t], b1 = same k+4.
// ---------------------------------------------------------------------------
__global__ void prep_wfrag_kernel(const float* __restrict__ w1, const float* __restrict__ w2,
                                  const float* __restrict__ w3, const float* __restrict__ w4) {
    const int f = blockIdx.x;        // 0..51
    const int lane = threadIdx.x;    // 0..31
    const int g = lane >> 2, t = lane & 3;
    float b0, b1;
    if (f < 48) {
        const int l = f >> 4, r = f & 15, kt = r >> 2, nt = r & 3;
        const float* W = (l == 0) ? w1 : (l == 1) ? w2 : w3;
        b0 = W[(8 * nt + g) * 32 + 8 * kt + t];
        b1 = W[(8 * nt + g) * 32 + 8 * kt + t + 4];
    } else {
        const int kt = f - 48;
        b0 = (g < 4) ? w4[g * 32 + 8 * kt + t]     : 0.0f;
        b1 = (g < 4) ? w4[g * 32 + 8 * kt + t + 4] : 0.0f;
    }
    const uint32_t h0 = __float_as_uint(b0) & 0xffffe000u;
    const uint32_t h1 = __float_as_uint(b1) & 0xffffe000u;
    float4 v;
    v.x = __uint_as_float(h0);
    v.y = __uint_as_float(h1);
    v.z = b0 - v.x;
    v.w = b1 - v.y;
    *(float4*)&g_wfrag[f * 128 + lane * 4] = v;
}

// ---------------------------------------------------------------------------
// Kernel 2: per-voxel transform grid (C,D,H,W) -> fp16 (D*H*W, 32) of W1 @ v.
// Block = 256 threads = 256 voxels. 3xTF32 mma for the 32x32 transform.
// ---------------------------------------------------------------------------
#define TC_STRIDE 264   // 264 mod 32 == 8 -> A-frag reads (8t+g) are conflict-free
__global__ void __launch_bounds__(256) voxel_w1_kernel(const float* __restrict__ g) {
    __shared__ float tile[32 * TC_STRIDE];   // 33,792 B  (c-major)
    __shared__ float swf[16 * 128];          //  8,192 B  (W1 frags)
    const int tid = threadIdx.x;
    const int v0 = blockIdx.x * 256;

    {
        const float4* src = (const float4*)g_wfrag;
        float4* dst = (float4*)swf;
        for (int i = tid; i < 16 * 32; i += 256) dst[i] = src[i];
    }
#pragma unroll
    for (int c = 0; c < 32; c++)
        tile[c * TC_STRIDE + tid] = g[(size_t)c * NVOX + v0 + tid];
    __syncthreads();

    const int warp = tid >> 5, lane = tid & 31;
    const int gq = lane >> 2, t = lane & 3;
    const int vb = warp * 32;

    float D[2][4][4];
#pragma unroll
    for (int mt = 0; mt < 2; mt++)
#pragma unroll
        for (int nt = 0; nt < 4; nt++)
#pragma unroll
            for (int i = 0; i < 4; i++) D[mt][nt][i] = 0.0f;

#pragma unroll
    for (int kt = 0; kt < 4; kt++) {
        uint32_t ah[2][4], al[2][4];
#pragma unroll
        for (int mt = 0; mt < 2; mt++) {
            const int r = vb + 16 * mt + gq;
            split1(tile[(8 * kt + t) * TC_STRIDE + r],         ah[mt][0], al[mt][0]);
            split1(tile[(8 * kt + t) * TC_STRIDE + r + 8],     ah[mt][1], al[mt][1]);
            split1(tile[(8 * kt + t + 4) * TC_STRIDE + r],     ah[mt][2], al[mt][2]);
            split1(tile[(8 * kt + t + 4) * TC_STRIDE + r + 8], ah[mt][3], al[mt][3]);
        }
#pragma unroll
        for (int nt = 0; nt < 4; nt++) {
            const float4 B = *(const float4*)&swf[(kt * 4 + nt) * 128 + lane * 4];
            const uint32_t bh0 = __float_as_uint(B.x), bh1 = __float_as_uint(B.y);
            const uint32_t bl0 = __float_as_uint(B.z), bl1 = __float_as_uint(B.w);
#pragma unroll
            for (int mt = 0; mt < 2; mt++) {
                mma_tf32(D[mt][nt], ah[mt][0], ah[mt][1], ah[mt][2], ah[mt][3], bh0, bh1);
                mma_tf32(D[mt][nt], al[mt][0], al[mt][1], al[mt][2], al[mt][3], bh0, bh1);
                mma_tf32(D[mt][nt], ah[mt][0], ah[mt][1], ah[mt][2], ah[mt][3], bl0, bl1);
            }
        }
    }
    // store fp16: D c0/c1 = (row g, cols 2t,2t+1), c2/c3 = row g+8
#pragma unroll
    for (int mt = 0; mt < 2; mt++)
#pragma unroll
        for (int nt = 0; nt < 4; nt++) {
            const int v = v0 + vb + 16 * mt + gq;
            const __half2 p0 = __floats2half2_rn(D[mt][nt][0], D[mt][nt][1]);
            const __half2 p1 = __floats2half2_rn(D[mt][nt][2], D[mt][nt][3]);
            *(__half2*)&g_vox16[(size_t)v * 32 + 8 * nt + 2 * t]       = p0;
            *(__half2*)&g_vox16[(size_t)(v + 8) * 32 + 8 * nt + 2 * t] = p1;
        }
}

// ---------------------------------------------------------------------------
// One mma stage, A built from previous D via warp shuffles.
// D layout (m16n8 acc): c0=(g,2t) c1=(g,2t+1) c2=(g+8,2t) c3=(g+8,2t+1).
// A layout (m16k8 tf32): a0=(g,t) a1=(g+8,t) a2=(g,t+4) a3=(g+8,t+4).
// ---------------------------------------------------------------------------
template <int FOFF, int BOFF, int NT>
__device__ __forceinline__ void mlp_stage_shfl(const float D[2][4][4], float Dn[2][4][4],
                                               const float* __restrict__ swf,
                                               const float* __restrict__ sb, int lane) {
    const int t = lane & 3;
    const int src0 = (lane & ~3) | (t >> 1);
    const int src2 = src0 + 2;
    const bool odd = (t & 1) != 0;

#pragma unroll
    for (int mt = 0; mt < 2; mt++)
#pragma unroll
        for (int nt = 0; nt < NT; nt++) {
            const float2 bb = *(const float2*)&sb[BOFF + 8 * nt + 2 * t];
            Dn[mt][nt][0] = bb.x; Dn[mt][nt][1] = bb.y;
            Dn[mt][nt][2] = bb.x; Dn[mt][nt][3] = bb.y;
        }
#pragma unroll
    for (int kt = 0; kt < 4; kt++) {
        uint32_t ah[2][4], al[2][4];
#pragma unroll
        for (int mt = 0; mt < 2; mt++) {
            const float r0 = D[mt][kt][0], r1 = D[mt][kt][1];
            const float r2 = D[mt][kt][2], r3 = D[mt][kt][3];
            const float e0 = __shfl_sync(FULLM, r0, src0);
            const float o0 = __shfl_sync(FULLM, r1, src0);
            const float e1 = __shfl_sync(FULLM, r2, src0);
            const float o1 = __shfl_sync(FULLM, r3, src0);
            const float e2 = __shfl_sync(FULLM, r0, src2);
            const float o2 = __shfl_sync(FULLM, r1, src2);
            const float e3 = __shfl_sync(FULLM, r2, src2);
            const float o3 = __shfl_sync(FULLM, r3, src2);
            split1(odd ? o0 : e0, ah[mt][0], al[mt][0]);
            split1(odd ? o1 : e1, ah[mt][1], al[mt][1]);
            split1(odd ? o2 : e2, ah[mt][2], al[mt][2]);
            split1(odd ? o3 : e3, ah[mt][3], al[mt][3]);
        }
#pragma unroll
        for (int nt = 0; nt < NT; nt++) {
            const int fidx = (NT == 4) ? (FOFF + kt * 4 + nt) : (FOFF + kt);
            const float4 B = *(const float4*)&swf[fidx * 128 + lane * 4];
            const uint32_t bh0 = __float_as_uint(B.x), bh1 = __float_as_uint(B.y);
            const uint32_t bl0 = __float_as_uint(B.z), bl1 = __float_as_uint(B.w);
#pragma unroll
            for (int mt = 0; mt < 2; mt++) {
                mma_tf32(Dn[mt][nt], ah[mt][0], ah[mt][1], ah[mt][2], ah[mt][3], bh0, bh1);
                mma_tf32(Dn[mt][nt], al[mt][0], al[mt][1], al[mt][2], al[mt][3], bh0, bh1);
                mma_tf32(Dn[mt][nt], ah[mt][0], ah[mt][1], ah[mt][2], ah[mt][3], bl0, bl1);
            }
        }
    }
}

// ---------------------------------------------------------------------------
// Kernel 3: fused gather (fp16 voxels) + 3 remaining MLP layers on tensor cores.
// smem: [ wfrag 36*128 | bias 128 | svf 256*36 ] = 13,952 floats = 55,808 B
// ---------------------------------------------------------------------------
#define SMEM_FLOATS (36 * 128 + 128 + 256 * 36)
#define SMEM_BYTES  (SMEM_FLOATS * 4)

__global__ void __launch_bounds__(256, 2) fused_field_kernel(
    const float* __restrict__ coord,
    const float* __restrict__ b1g, const float* __restrict__ b2g,
    const float* __restrict__ b3g, const float* __restrict__ b4g,
    float* __restrict__ out)
{
    extern __shared__ float sm[];
    float* swf = sm;                      // 36*128 (frags 16..51 of g_wfrag)
    float* sb  = sm + 36 * 128;           // 128: b1 | b2 | b3 | b4(pad)
    float* svf = sm + 36 * 128 + 128;     // 256 points * stride 36

    const int tid = threadIdx.x;
    {
        const float4* src = (const float4*)(g_wfrag + 16 * 128);
        float4* dst = (float4*)swf;
        for (int i = tid; i < 36 * 32; i += 256) dst[i] = src[i];
        if (tid < 32) {
            sb[tid]      = b1g[tid];
            sb[32 + tid] = b2g[tid];
            sb[64 + tid] = b3g[tid];
            sb[96 + tid] = (tid < 4) ? b4g[tid] : 0.0f;
        }
    }
    __syncthreads();

    const int warp  = tid >> 5;
    const int lane  = tid & 31;
    const int chunk = lane & 3;        // 16B (8-half) slice of the 32 channels
    const int psub  = lane >> 2;       // point-of-8 in round

    // --- Phase 1: warp-cooperative trilinear gather of h1-pre -> svf ---
#pragma unroll 1
    for (int s = 0; s < 4; s++) {
        const int q   = (warp << 5) + (s << 3) + psub;
        const int pid = blockIdx.x * 256 + q;

        const float cx = __ldg(&coord[pid * 3 + 0]);
        const float cy = __ldg(&coord[pid * 3 + 1]);
        const float cz = __ldg(&coord[pid * 3 + 2]);

        const float fx = (cx + 1.0f) * 64.0f - 0.5f;
        const float fy = (cy + 1.0f) * 64.0f - 0.5f;
        const float fz = (cz + 1.0f) * 64.0f - 0.5f;

        const float x0f = floorf(fx), y0f = floorf(fy), z0f = floorf(fz);
        const float tx = fx - x0f, ty = fy - y0f, tz = fz - z0f;
        const int x0 = (int)x0f, y0 = (int)y0f, z0 = (int)z0f;

        int   xs[2], ys[2], zs[2];
        float wx[2], wy[2], wz[2];
        xs[0] = max(x0, 0);        xs[1] = min(x0 + 1, RES - 1);
        ys[0] = max(y0, 0);        ys[1] = min(y0 + 1, RES - 1);
        zs[0] = max(z0, 0);        zs[1] = min(z0 + 1, RES - 1);
        wx[0] = (x0 >= 0)          ? (1.0f - tx) : 0.0f;
        wx[1] = (x0 + 1 <= RES - 1)? tx          : 0.0f;
        wy[0] = (y0 >= 0)          ? (1.0f - ty) : 0.0f;
        wy[1] = (y0 + 1 <= RES - 1)? ty          : 0.0f;
        wz[0] = (z0 >= 0)          ? (1.0f - tz) : 0.0f;
        wz[1] = (z0 + 1 <= RES - 1)? tz          : 0.0f;

        float acc[8];
#pragma unroll
        for (int i = 0; i < 8; i++) acc[i] = 0.0f;

#pragma unroll
        for (int kz = 0; kz < 2; kz++)
#pragma unroll
            for (int ky = 0; ky < 2; ky++)
#pragma unroll
                for (int kx = 0; kx < 2; kx++) {
                    const float w = wz[kz] * wy[ky] * wx[kx];
                    const int   vox = ((zs[kz] * RES + ys[ky]) * RES + xs[kx]);
                    const uint4 raw = __ldg(((const uint4*)(g_vox16 + ((size_t)vox << 5))) + chunk);
                    const __half2* h2 = (const __half2*)&raw;
                    const float2 f0 = __half22float2(h2[0]);
                    const float2 f1 = __half22float2(h2[1]);
                    const float2 f2 = __half22float2(h2[2]);
                    const float2 f3 = __half22float2(h2[3]);
                    acc[0] = fmaf(w, f0.x, acc[0]);  acc[1] = fmaf(w, f0.y, acc[1]);
                    acc[2] = fmaf(w, f1.x, acc[2]);  acc[3] = fmaf(w, f1.y, acc[3]);
                    acc[4] = fmaf(w, f2.x, acc[4]);  acc[5] = fmaf(w, f2.y, acc[5]);
                    acc[6] = fmaf(w, f3.x, acc[6]);  acc[7] = fmaf(w, f3.y, acc[7]);
                }
        *(float4*)&svf[q * 36 + chunk * 8]     = make_float4(acc[0], acc[1], acc[2], acc[3]);
        *(float4*)&svf[q * 36 + chunk * 8 + 4] = make_float4(acc[4], acc[5], acc[6], acc[7]);
    }
    __syncwarp();

    // --- Phase 2: layers 2..4 on tensor cores (3xTF32) ---
    const int gq = lane >> 2, t = lane & 3;

    float bA[8];
#pragma unroll
    for (int kt = 0; kt < 4; kt++) {
        bA[2 * kt]     = sb[8 * kt + t];       // b1[8kt+t]
        bA[2 * kt + 1] = sb[8 * kt + t + 4];   // b1[8kt+t+4]
    }

    float D[2][4][4], Dn[2][4][4];

    // stage 1 (= layer 2): A = relu(svf + b1), W = W2 (frags local 0..15), init b2
#pragma unroll
    for (int mt = 0; mt < 2; mt++)
#pragma unroll
        for (int nt = 0; nt < 4; nt++) {
            const float2 bb = *(const float2*)&sb[32 + 8 * nt + 2 * t];
            D[mt][nt][0] = bb.x; D[mt][nt][1] = bb.y;
            D[mt][nt][2] = bb.x; D[mt][nt][3] = bb.y;
        }
#pragma unroll
    for (int kt = 0; kt < 4; kt++) {
        uint32_t ah[2][4], al[2][4];
#pragma unroll
        for (int mt = 0; mt < 2; mt++) {
            const int q0 = warp * 32 + 16 * mt + gq;
            const float x0 = fmaxf(svf[q0 * 36 + 8 * kt + t]           + bA[2 * kt],     0.0f);
            const float x1 = fmaxf(svf[(q0 + 8) * 36 + 8 * kt + t]     + bA[2 * kt],     0.0f);
            const float x2 = fmaxf(svf[q0 * 36 + 8 * kt + t + 4]       + bA[2 * kt + 1], 0.0f);
            const float x3 = fmaxf(svf[(q0 + 8) * 36 + 8 * kt + t + 4] + bA[2 * kt + 1], 0.0f);
            split1(x0, ah[mt][0], al[mt][0]);
            split1(x1, ah[mt][1], al[mt][1]);
            split1(x2, ah[mt][2], al[mt][2]);
            split1(x3, ah[mt][3], al[mt][3]);
        }
#pragma unroll
        for (int nt = 0; nt < 4; nt++) {
            const float4 B = *(const float4*)&swf[(kt * 4 + nt) * 128 + lane * 4];
            const uint32_t bh0 = __float_as_uint(B.x), bh1 = __float_as_uint(B.y);
            const uint32_t bl0 = __float_as_uint(B.z), bl1 = __float_as_uint(B.w);
#pragma unroll
            for (int mt = 0; mt < 2; mt++) {
                mma_tf32(D[mt][nt], ah[mt][0], ah[mt][1], ah[mt][2], ah[mt][3], bh0, bh1);
                mma_tf32(D[mt][nt], al[mt][0], al[mt][1], al[mt][2], al[mt][3], bh0, bh1);
                mma_tf32(D[mt][nt], ah[mt][0], ah[mt][1], ah[mt][2], ah[mt][3], bl0, bl1);
            }
        }
    }
#pragma unroll
    for (int mt = 0; mt < 2; mt++)
#pragma unroll
        for (int nt = 0; nt < 4; nt++)
#pragma unroll
            for (int i = 0; i < 4; i++) D[mt][nt][i] = fmaxf(D[mt][nt][i], 0.0f);

    // stage 2 (= layer 3): W3 frags local 16..31, init b3
    mlp_stage_shfl<16, 64, 4>(D, Dn, swf, sb, lane);
#pragma unroll
    for (int mt = 0; mt < 2; mt++)
#pragma unroll
        for (int nt = 0; nt < 4; nt++)
#pragma unroll
            for (int i = 0; i < 4; i++) Dn[mt][nt][i] = fmaxf(Dn[mt][nt][i], 0.0f);

    // stage 3 (= layer 4): W4 frags local 32..35, init b4, no relu
    mlp_stage_shfl<32, 96, 1>(Dn, D, swf, sb, lane);

    // store: c0/c1 = (row g, cols 2t,2t+1), c2/c3 = (row g+8); valid cols < 4.
    if (t < 2) {
        const int base = blockIdx.x * 256 + warp * 32;
#pragma unroll
        for (int mt = 0; mt < 2; mt++) {
            const int p0 = base + 16 * mt + gq;
            *(float2*)&out[p0 * 4 + 2 * t]       = make_float2(D[mt][0][0], D[mt][0][1]);
            *(float2*)&out[(p0 + 8) * 4 + 2 * t] = make_float2(D[mt][0][2], D[mt][0][3]);
        }
    }
}

// ---------------------------------------------------------------------------
extern "C" void kernel_launch(void* const* d_in, const int* in_sizes, int n_in,
                              void* d_out, int out_size)
{
    const float* coord = (const float*)d_in[0];
    const float* grid  = (const float*)d_in[1];
    const float* w1 = (const float*)d_in[2];
    const float* b1 = (const float*)d_in[3];
    const float* w2 = (const float*)d_in[4];
    const float* b2 = (const float*)d_in[5];
    const float* w3 = (const float*)d_in[6];
    const float* b3 = (const float*)d_in[7];
    const float* w4 = (const float*)d_in[8];
    const float* b4 = (const float*)d_in[9];
    float* out = (float*)d_out;

    cudaFuncSetAttribute(fused_field_kernel,
                         cudaFuncAttributeMaxDynamicSharedMemorySize, SMEM_BYTES);

    prep_wfrag_kernel<<<52, 32>>>(w1, w2, w3, w4);
    voxel_w1_kernel<<<NVOX / 256, 256>>>(grid);
    fused_field_kernel<<<NPTS / 256, 256, SMEM_BYTES>>>(coord, b1, b2, b3, b4, out);
}